// round 4
// baseline (speedup 1.0000x reference)
#include <cuda_runtime.h>
#include <cuda_bf16.h>
#include <mma.h>
#include <cuda_pipeline.h>
#include <math.h>

using namespace nvcuda;

#define BB 64
#define SS 512
#define DD 1024
#define HH 1024

// Scratch (device globals — allocation-free rule)
__device__ float g_h[2][BB * HH];                       // tf32-rounded h, double buffered
__device__ float g_xg[(size_t)SS * BB * 4 * HH];        // precomputed x @ W_in  [S][B][4][H]
__device__ unsigned g_cnt = 0;
__device__ unsigned g_gen = 0;

// ---------------------------------------------------------------------------
// Hand-rolled grid barrier (all blocks guaranteed co-resident: 1 block/SM)
// ---------------------------------------------------------------------------
__device__ __forceinline__ void grid_sync(unsigned nb) {
    __threadfence();          // make this thread's global writes visible (L2)
    __syncthreads();
    if (threadIdx.x == 0) {
        volatile unsigned* genp = &g_gen;
        unsigned old = *genp;
        __threadfence();
        if (atomicAdd(&g_cnt, 1u) == nb - 1u) {
            g_cnt = 0u;
            __threadfence();
            *genp = old + 1u;
        } else {
            while (*genp == old) { }
        }
    }
    __syncthreads();
}

// ---------------------------------------------------------------------------
// Phase 1: xg[s*B+b][g*H+j] = sum_d x[b][s][d] * W_in[g][d][j]
// tf32 wmma GEMM, 128x128 tile, BK=32, double-buffered smem.
// ---------------------------------------------------------------------------
__global__ void __launch_bounds__(256)
xw_gemm(const float* __restrict__ x, const float* __restrict__ Win)
{
    extern __shared__ float sm1[];
    float* As = sm1;                    // [2][128][40]  (pad 40 -> 160B rows)
    float* Bs = sm1 + 2 * 128 * 40;     // [2][32][136]  (pad 136 -> 544B rows)

    const int tid  = threadIdx.x;
    const int warp = tid >> 5;
    const int wm   = warp >> 2;     // 0..1 : 64-row half
    const int wn   = warp & 3;      // 0..3 : 32-col slice
    const int row0 = blockIdx.y * 128;
    const int col0 = blockIdx.x * 128;
    const int g    = col0 >> 10;    // gate (tile never straddles a gate: 1024 % 128 == 0)
    const int j0   = col0 & 1023;
    const float* Wg = Win + (size_t)g * (DD * HH);

    const int ac4 = tid & 7;        // A float4-column group (0..7)
    const int bc4 = tid & 31;       // B float4-column group (0..31)
    const int bkr = tid >> 5;       // B base k-row (0..7)

    // Per-thread A source rows (output row r = s*B + b  ->  x row (b,s))
    const float* arow[4];
    int arows[4];
#pragma unroll
    for (int i = 0; i < 4; i++) {
        int q = tid + 256 * i;
        int r = q >> 3;
        arows[i] = r;
        int m = row0 + r;
        int s = m >> 6, b = m & 63;
        arow[i] = x + ((size_t)b * SS + s) * DD + ac4 * 4;
    }

    wmma::fragment<wmma::accumulator, 16, 16, 8, float> acc[4][2];
#pragma unroll
    for (int i = 0; i < 4; i++)
#pragma unroll
        for (int j = 0; j < 2; j++) wmma::fill_fragment(acc[i][j], 0.0f);

    float4 ra[4], rb[4];

#define P1_LOAD(kc_) {                                                          \
    for (int i_ = 0; i_ < 4; i_++)                                              \
        ra[i_] = *(const float4*)(arow[i_] + (kc_));                            \
    for (int i_ = 0; i_ < 4; i_++)                                              \
        rb[i_] = *(const float4*)(Wg + (size_t)((kc_) + bkr + 8 * i_) * HH      \
                                      + j0 + bc4 * 4);                          \
}

#define P1_STS(p_) {                                                            \
    for (int i_ = 0; i_ < 4; i_++) {                                            \
        float4 t_;                                                              \
        t_.x = wmma::__float_to_tf32(ra[i_].x);                                 \
        t_.y = wmma::__float_to_tf32(ra[i_].y);                                 \
        t_.z = wmma::__float_to_tf32(ra[i_].z);                                 \
        t_.w = wmma::__float_to_tf32(ra[i_].w);                                 \
        *(float4*)(As + (p_) * 5120 + arows[i_] * 40 + ac4 * 4) = t_;           \
    }                                                                           \
    for (int i_ = 0; i_ < 4; i_++) {                                            \
        float4 t_;                                                              \
        t_.x = wmma::__float_to_tf32(rb[i_].x);                                 \
        t_.y = wmma::__float_to_tf32(rb[i_].y);                                 \
        t_.z = wmma::__float_to_tf32(rb[i_].z);                                 \
        t_.w = wmma::__float_to_tf32(rb[i_].w);                                 \
        *(float4*)(Bs + (p_) * 4352 + (bkr + 8 * i_) * 136 + bc4 * 4) = t_;     \
    }                                                                           \
}

    // prologue
    P1_LOAD(0);
    P1_STS(0);
    __syncthreads();

    int p = 0;
    for (int it = 0; it < 32; ++it) {
        if (it < 31) { P1_LOAD((it + 1) * 32); }   // prefetch (hidden under mma)

        wmma::fragment<wmma::matrix_a, 16, 16, 8, wmma::precision::tf32, wmma::row_major> af[4];
        wmma::fragment<wmma::matrix_b, 16, 16, 8, wmma::precision::tf32, wmma::row_major> bf[2];
#pragma unroll
        for (int kk = 0; kk < 32; kk += 8) {
#pragma unroll
            for (int i = 0; i < 4; i++)
                wmma::load_matrix_sync(af[i], As + p * 5120 + (wm * 64 + i * 16) * 40 + kk, 40);
#pragma unroll
            for (int j = 0; j < 2; j++)
                wmma::load_matrix_sync(bf[j], Bs + p * 4352 + kk * 136 + wn * 32 + j * 16, 136);
#pragma unroll
            for (int i = 0; i < 4; i++)
#pragma unroll
                for (int j = 0; j < 2; j++)
                    wmma::mma_sync(acc[i][j], af[i], bf[j], acc[i][j]);
        }
        __syncthreads();
        if (it < 31) {
            P1_STS(p ^ 1);
            __syncthreads();
            p ^= 1;
        }
    }

    // epilogue: store to g_xg (bias added in phase 2)
#pragma unroll
    for (int i = 0; i < 4; i++)
#pragma unroll
        for (int j = 0; j < 2; j++) {
            float* dst = g_xg + (size_t)(row0 + wm * 64 + i * 16) * 4096
                              + col0 + wn * 32 + j * 16;
            wmma::store_matrix_sync(dst, acc[i][j], 4096, wmma::mem_row_major);
        }
#undef P1_LOAD
#undef P1_STS
}

// ---------------------------------------------------------------------------
// Phase 2: persistent recurrence. 128 blocks, each owns 8 h-columns (32 gate
// columns). W_hid slice (tf32) resident in smem for all 512 steps; c slice in
// smem. Per step: stream full h (cp.async, L2), 8 warps x 128 tf32 mmas,
// elementwise gates, write outputs, grid barrier.
// ---------------------------------------------------------------------------
__global__ void __launch_bounds__(256)
lstm_rec(const float* __restrict__ hin, const float* __restrict__ cin,
         const float* __restrict__ Whid, const float* __restrict__ bias,
         float* __restrict__ out)
{
    extern __shared__ float sm[];
    float* Wsm = sm;                    // [1024][40]  (n = g*8+jj, pad 40)
    float* As  = Wsm + 1024 * 40;       // [2][64][72] h chunk, double buffered
    float* gsm = As + 2 * 64 * 72;      // [64][32] gate accumulators
    float* csm = gsm + 64 * 32;         // [64][8] cell state (persistent)
    float* bsm = csm + 512;             // [32] bias slice

    const int tid  = threadIdx.x;
    const int warp = tid >> 5;
    const int mi   = warp >> 1;         // 0..3 : 16-row tile
    const int ni   = warp & 1;          // 0..1 : 16-col tile
    const int j0   = blockIdx.x * 8;    // this block's h-column base
    const unsigned NB = gridDim.x;

    // one-time: resident weights (tf32-rounded), bias, c, initial h
    for (int q = tid; q < 1024 * 32; q += 256) {
        int k = q >> 5, n = q & 31, gg = n >> 3, jj = n & 7;
        Wsm[k * 40 + n] =
            wmma::__float_to_tf32(Whid[((size_t)gg * HH + k) * HH + j0 + jj]);
    }
    if (tid < 32)
        bsm[tid] = bias[(tid >> 3) * HH + j0 + (tid & 7)];
    for (int idx = tid; idx < 512; idx += 256) {
        int r = idx >> 3, jj = idx & 7;
        csm[idx] = cin[r * HH + j0 + jj];
        g_h[0][r * HH + j0 + jj] = wmma::__float_to_tf32(hin[r * HH + j0 + jj]);
    }
    grid_sync(NB);

    for (int s = 0; s < SS; ++s) {
        const float* hcur = g_h[s & 1];
        float*       hnxt = g_h[(s & 1) ^ 1];

        wmma::fragment<wmma::accumulator, 16, 16, 8, float> acc;
        wmma::fill_fragment(acc, 0.0f);

        // issue chunk 0 (cp.async.cg — bypasses stale L1, lands in smem)
        {
            float* dstbuf = As;
#pragma unroll
            for (int i = 0; i < 4; i++) {
                int q = tid + 256 * i;
                int r = q >> 4, c4 = q & 15;
                __pipeline_memcpy_async(dstbuf + r * 72 + c4 * 4,
                                        hcur + r * HH + c4 * 4, 16);
            }
            __pipeline_commit();
        }

        for (int it = 0; it < 16; ++it) {
            if (it < 15) {
                int kc = (it + 1) * 64;
                float* dstbuf = As + ((it + 1) & 1) * 4608;
#pragma unroll
                for (int i = 0; i < 4; i++) {
                    int q = tid + 256 * i;
                    int r = q >> 4, c4 = q & 15;
                    __pipeline_memcpy_async(dstbuf + r * 72 + c4 * 4,
                                            hcur + r * HH + kc + c4 * 4, 16);
                }
                __pipeline_commit();
                __pipeline_wait_prior(1);
            } else {
                __pipeline_wait_prior(0);
            }
            __syncthreads();

            const float* abuf = As + (it & 1) * 4608;
            const int kc0 = it * 64;
            wmma::fragment<wmma::matrix_a, 16, 16, 8, wmma::precision::tf32, wmma::row_major> af;
            wmma::fragment<wmma::matrix_b, 16, 16, 8, wmma::precision::tf32, wmma::row_major> bf;
#pragma unroll
            for (int k8 = 0; k8 < 64; k8 += 8) {
                wmma::load_matrix_sync(af, abuf + (mi * 16) * 72 + k8, 72);
                wmma::load_matrix_sync(bf, Wsm + (kc0 + k8) * 40 + ni * 16, 40);
                wmma::mma_sync(acc, af, bf, acc);
            }
            __syncthreads();
        }

        wmma::store_matrix_sync(gsm + (mi * 16) * 32 + ni * 16, acc, 32,
                                wmma::mem_row_major);
        __syncthreads();

        // elementwise gates + state update + outputs
        const float* xgp = g_xg + (size_t)s * BB * 4096;
        for (int idx = tid; idx < 512; idx += 256) {
            int r = idx >> 3, jj = idx & 7;
            const float* xr = xgp + (size_t)r * 4096 + j0 + jj;
            float gf = gsm[r * 32 +      jj] + xr[0]    + bsm[jj];
            float gi = gsm[r * 32 +  8 + jj] + xr[1024] + bsm[8 + jj];
            float go = gsm[r * 32 + 16 + jj] + xr[2048] + bsm[16 + jj];
            float ga = gsm[r * 32 + 24 + jj] + xr[3072] + bsm[24 + jj];
            float f  = 1.0f / (1.0f + expf(-gf));
            float ii = 1.0f / (1.0f + expf(-gi));
            float oo = 1.0f / (1.0f + expf(-go));
            float aa = tanhf(ga);
            float cn = f * csm[idx] + ii * aa;
            float hv = tanhf(cn) * oo;
            csm[idx] = cn;
            size_t ob = ((size_t)r * SS + s) * HH + j0 + jj;
            out[ob] = hv;                               // hs [B,S,H]
            out[(size_t)BB * SS * HH + ob] = cn;        // cs [B,S,H]
            hnxt[r * HH + j0 + jj] = wmma::__float_to_tf32(hv);
        }
        grid_sync(NB);
    }
}

// ---------------------------------------------------------------------------
extern "C" void kernel_launch(void* const* d_in, const int* in_sizes, int n_in,
                              void* d_out, int out_size)
{
    const float* x    = (const float*)d_in[0];
    const float* h0   = (const float*)d_in[1];
    const float* c0   = (const float*)d_in[2];
    const float* Win  = (const float*)d_in[3];
    const float* Whid = (const float*)d_in[4];
    const float* bias = (const float*)d_in[5];
    float* out = (float*)d_out;

    const int SMEM1 = (2 * 128 * 40 + 2 * 32 * 136) * 4;                 // 75776 B
    const int SMEM2 = (1024 * 40 + 2 * 64 * 72 + 64 * 32 + 512 + 32) * 4; // 211072 B

    cudaFuncSetAttribute(xw_gemm,  cudaFuncAttributeMaxDynamicSharedMemorySize, SMEM1);
    cudaFuncSetAttribute(lstm_rec, cudaFuncAttributeMaxDynamicSharedMemorySize, SMEM2);

    // Phase 1: xg = x @ W_in   (grid: 32 col-tiles x 256 row-tiles)
    xw_gemm<<<dim3(32, 256), 256, SMEM1>>>(x, Win);

    // Phase 2: persistent recurrence, 128 blocks (1/SM, all co-resident)
    lstm_rec<<<128, 256, SMEM2>>>(h0, c0, Whid, bias, out);
}

// round 5
// speedup vs baseline: 1.0683x; 1.0683x over previous
#include <cuda_runtime.h>
#include <cuda_bf16.h>
#include <mma.h>
#include <cuda_pipeline.h>
#include <math.h>

using namespace nvcuda;

#define BB 64
#define SS 512
#define DD 1024
#define HH 1024

// Scratch (device globals — allocation-free rule)
__device__ float g_h[2][BB * HH];                       // tf32-rounded h, double buffered
__device__ float g_xg[(size_t)SS * 4 * HH * BB];        // x @ W_in, laid out [S][4][H][B]
__device__ unsigned g_cnt = 0;
__device__ unsigned g_gen = 0;

// ---------------------------------------------------------------------------
// Hand-rolled grid barrier (all blocks co-resident: 1 block/SM)
// ---------------------------------------------------------------------------
__device__ __forceinline__ void grid_sync(unsigned nb) {
    __threadfence();
    __syncthreads();
    if (threadIdx.x == 0) {
        volatile unsigned* genp = &g_gen;
        unsigned old = *genp;
        __threadfence();
        if (atomicAdd(&g_cnt, 1u) == nb - 1u) {
            g_cnt = 0u;
            __threadfence();
            *genp = old + 1u;
        } else {
            while (*genp == old) { }
        }
    }
    __syncthreads();
}

__device__ __forceinline__ float fsig(float x) {
    x = fminf(fmaxf(x, -30.f), 30.f);
    float e = __expf(-x);
    return __fdividef(1.f, 1.f + e);
}
__device__ __forceinline__ float ftanh(float x) {
    x = fminf(fmaxf(x, -15.f), 15.f);
    float e = __expf(2.f * x);
    return __fdividef(e - 1.f, e + 1.f);
}

// ---------------------------------------------------------------------------
// Phase 1: xg = x @ W_in, tf32 wmma, 128x128 tile, BK=32, double-buffered.
// Output stored as [S][4][H][B] (col-major store) for coalesced phase-2 reads.
// ---------------------------------------------------------------------------
__global__ void __launch_bounds__(256)
xw_gemm(const float* __restrict__ x, const float* __restrict__ Win)
{
    extern __shared__ float sm1[];
    float* As = sm1;                    // [2][128][40]
    float* Bs = sm1 + 2 * 128 * 40;     // [2][32][136]

    const int tid  = threadIdx.x;
    const int warp = tid >> 5;
    const int wm   = warp >> 2;     // 0..1 : 64-row half (one s each)
    const int wn   = warp & 3;      // 0..3 : 32-col slice
    const int row0 = blockIdx.y * 128;
    const int col0 = blockIdx.x * 128;
    const int g    = col0 >> 10;    // gate (tile never straddles a gate)
    const int j0   = col0 & 1023;
    const int s0   = row0 >> 6;
    const float* Wg = Win + (size_t)g * (DD * HH);

    const int ac4 = tid & 7;
    const int bc4 = tid & 31;
    const int bkr = tid >> 5;

    const float* arow[4];
    int arows[4];
#pragma unroll
    for (int i = 0; i < 4; i++) {
        int q = tid + 256 * i;
        int r = q >> 3;
        arows[i] = r;
        int m = row0 + r;
        int s = m >> 6, b = m & 63;
        arow[i] = x + ((size_t)b * SS + s) * DD + ac4 * 4;
    }

    wmma::fragment<wmma::accumulator, 16, 16, 8, float> acc[4][2];
#pragma unroll
    for (int i = 0; i < 4; i++)
#pragma unroll
        for (int j = 0; j < 2; j++) wmma::fill_fragment(acc[i][j], 0.0f);

    float4 ra[4], rb[4];

#define P1_LOAD(kc_) {                                                          \
    for (int i_ = 0; i_ < 4; i_++)                                              \
        ra[i_] = *(const float4*)(arow[i_] + (kc_));                            \
    for (int i_ = 0; i_ < 4; i_++)                                              \
        rb[i_] = *(const float4*)(Wg + (size_t)((kc_) + bkr + 8 * i_) * HH      \
                                      + j0 + bc4 * 4);                          \
}

#define P1_STS(p_) {                                                            \
    for (int i_ = 0; i_ < 4; i_++) {                                            \
        float4 t_;                                                              \
        t_.x = wmma::__float_to_tf32(ra[i_].x);                                 \
        t_.y = wmma::__float_to_tf32(ra[i_].y);                                 \
        t_.z = wmma::__float_to_tf32(ra[i_].z);                                 \
        t_.w = wmma::__float_to_tf32(ra[i_].w);                                 \
        *(float4*)(As + (p_) * 5120 + arows[i_] * 40 + ac4 * 4) = t_;           \
    }                                                                           \
    for (int i_ = 0; i_ < 4; i_++) {                                            \
        float4 t_;                                                              \
        t_.x = wmma::__float_to_tf32(rb[i_].x);                                 \
        t_.y = wmma::__float_to_tf32(rb[i_].y);                                 \
        t_.z = wmma::__float_to_tf32(rb[i_].z);                                 \
        t_.w = wmma::__float_to_tf32(rb[i_].w);                                 \
        *(float4*)(Bs + (p_) * 4352 + (bkr + 8 * i_) * 136 + bc4 * 4) = t_;     \
    }                                                                           \
}

    P1_LOAD(0);
    P1_STS(0);
    __syncthreads();

    int p = 0;
    for (int it = 0; it < 32; ++it) {
        if (it < 31) { P1_LOAD((it + 1) * 32); }

        wmma::fragment<wmma::matrix_a, 16, 16, 8, wmma::precision::tf32, wmma::row_major> af[4];
        wmma::fragment<wmma::matrix_b, 16, 16, 8, wmma::precision::tf32, wmma::row_major> bf[2];
#pragma unroll
        for (int kk = 0; kk < 32; kk += 8) {
#pragma unroll
            for (int i = 0; i < 4; i++)
                wmma::load_matrix_sync(af[i], As + p * 5120 + (wm * 64 + i * 16) * 40 + kk, 40);
#pragma unroll
            for (int j = 0; j < 2; j++)
                wmma::load_matrix_sync(bf[j], Bs + p * 4352 + kk * 136 + wn * 32 + j * 16, 136);
#pragma unroll
            for (int i = 0; i < 4; i++)
#pragma unroll
                for (int j = 0; j < 2; j++)
                    wmma::mma_sync(acc[i][j], af[i], bf[j], acc[i][j]);
        }
        __syncthreads();
        if (it < 31) {
            P1_STS(p ^ 1);
            __syncthreads();
            p ^= 1;
        }
    }

    // epilogue: col-major store into [S][4][H][B]  (b fastest)
    {
        float* base = g_xg + (size_t)(s0 + wm) * (4 * HH * BB)
                           + (size_t)g * (HH * BB);
#pragma unroll
        for (int i = 0; i < 4; i++)
#pragma unroll
            for (int j = 0; j < 2; j++) {
                float* dst = base + (size_t)(j0 + wn * 32 + j * 16) * BB + i * 16;
                wmma::store_matrix_sync(dst, acc[i][j], BB, wmma::mem_col_major);
            }
    }
#undef P1_LOAD
#undef P1_STS
}

// ---------------------------------------------------------------------------
// Phase 2: persistent recurrence. 128 blocks x 8 h-cols (32 gate cols).
// W_hid slice resident in smem (tf32). 4-stage cp.async pipeline (k=32
// chunks, 1 barrier/chunk). 8 warps = 4 row-tiles x 2 k-halves, each warp
// 16x32 output. xg slice prefetched via cp.async ([S][4][H][B] layout).
// ---------------------------------------------------------------------------
__global__ void __launch_bounds__(256)
lstm_rec(const float* __restrict__ hin, const float* __restrict__ cin,
         const float* __restrict__ Whid, const float* __restrict__ bias,
         float* __restrict__ out)
{
    extern __shared__ float sm[];
    float* Wsm = sm;                        // [1024][36]  (n = g*8+jj)
    float* As  = Wsm + 1024 * 36;           // [4 stages][64][36] h chunks
    float* gsm = As + 4 * 64 * 36;          // [2 k-halves][64][36] partials
    float* xgs = gsm + 2 * 64 * 36;         // [32 gj][68] xg slice (pad 68)
    float* csm = xgs + 32 * 68;             // [64][8] cell state
    float* bsm = csm + 512;                 // [32] bias slice

    const int tid  = threadIdx.x;
    const int warp = tid >> 5;
    const int mi   = warp & 3;          // row-tile (16 rows)
    const int wk   = warp >> 2;         // k-half (0/1)
    const int j0   = blockIdx.x * 8;
    const unsigned NB = gridDim.x;

    // one-time init
    for (int q = tid; q < 1024 * 32; q += 256) {
        int k = q >> 5, n = q & 31, gg = n >> 3, jj = n & 7;
        Wsm[k * 36 + n] =
            wmma::__float_to_tf32(Whid[((size_t)gg * HH + k) * HH + j0 + jj]);
    }
    if (tid < 32)
        bsm[tid] = bias[(tid >> 3) * HH + j0 + (tid & 7)];
    for (int idx = tid; idx < 512; idx += 256) {
        int r = idx >> 3, jj = idx & 7;
        csm[idx] = cin[r * HH + j0 + jj];
        g_h[0][r * HH + j0 + jj] = wmma::__float_to_tf32(hin[r * HH + j0 + jj]);
    }
    grid_sync(NB);

    for (int s = 0; s < SS; ++s) {
        const float* hcur = g_h[s & 1];
        float*       hnxt = g_h[(s & 1) ^ 1];
        const float* xgp  = g_xg + (size_t)s * (4 * HH * BB);

#define ISSUE_CHUNK(c_, st_) {                                                  \
    float* dst_ = As + (st_) * 2304;                                            \
    const float* src_ = hcur + (c_) * 32;                                       \
    _Pragma("unroll")                                                           \
    for (int i_ = 0; i_ < 2; i_++) {                                            \
        int m_ = tid + 256 * i_;                                                \
        int r_ = m_ >> 3, c4_ = m_ & 7;                                         \
        __pipeline_memcpy_async(dst_ + r_ * 36 + c4_ * 4,                       \
                                src_ + r_ * HH + c4_ * 4, 16);                  \
    }                                                                           \
}
        // prologue: chunks 0..2 + xg slice (group0 carries xg)
        ISSUE_CHUNK(0, 0);
#pragma unroll
        for (int i = 0; i < 2; i++) {          // xg: 32 segs x 64 floats
            int m = tid + 256 * i;             // m in [0,512): 16B units
            int gj = m >> 4, q = m & 15;
            int gg = gj >> 3, jj = gj & 7;
            __pipeline_memcpy_async(xgs + gj * 68 + q * 4,
                                    xgp + (size_t)gg * (HH * BB)
                                        + (j0 + jj) * BB + q * 4, 16);
        }
        __pipeline_commit();
        ISSUE_CHUNK(1, 1); __pipeline_commit();
        ISSUE_CHUNK(2, 2); __pipeline_commit();

        wmma::fragment<wmma::accumulator, 16, 16, 8, float> acc0, acc1;
        wmma::fill_fragment(acc0, 0.0f);
        wmma::fill_fragment(acc1, 0.0f);

        for (int it = 0; it < 32; ++it) {
            __pipeline_wait_prior(2);
            __syncthreads();
            if (it < 29) { ISSUE_CHUNK(it + 3, (it + 3) & 3); }
            __pipeline_commit();

            const float* abuf = As + (it & 3) * 2304;
            const int kb = it * 32 + wk * 16;
            wmma::fragment<wmma::matrix_a, 16, 16, 8, wmma::precision::tf32, wmma::row_major> af;
            wmma::fragment<wmma::matrix_b, 16, 16, 8, wmma::precision::tf32, wmma::row_major> bf0, bf1;
#pragma unroll
            for (int k8 = 0; k8 < 16; k8 += 8) {
                wmma::load_matrix_sync(af, abuf + (mi * 16) * 36 + wk * 16 + k8, 36);
                wmma::load_matrix_sync(bf0, Wsm + (kb + k8) * 36, 36);
                wmma::load_matrix_sync(bf1, Wsm + (kb + k8) * 36 + 16, 36);
                wmma::mma_sync(acc0, af, bf0, acc0);
                wmma::mma_sync(acc1, af, bf1, acc1);
            }
        }
#undef ISSUE_CHUNK

        // reduce k-halves through gsm
        wmma::store_matrix_sync(gsm + wk * 2304 + (mi * 16) * 36,      acc0, 36,
                                wmma::mem_row_major);
        wmma::store_matrix_sync(gsm + wk * 2304 + (mi * 16) * 36 + 16, acc1, 36,
                                wmma::mem_row_major);
        __syncthreads();

        // gates + state update + outputs
        for (int idx = tid; idx < 512; idx += 256) {
            int r = idx >> 3, jj = idx & 7;
            const float* p0 = gsm + r * 36;
            const float* p1 = gsm + 2304 + r * 36;
            float gf = p0[jj]      + p1[jj]      + xgs[jj * 68 + r]        + bsm[jj];
            float gi = p0[8 + jj]  + p1[8 + jj]  + xgs[(8 + jj) * 68 + r]  + bsm[8 + jj];
            float go = p0[16 + jj] + p1[16 + jj] + xgs[(16 + jj) * 68 + r] + bsm[16 + jj];
            float ga = p0[24 + jj] + p1[24 + jj] + xgs[(24 + jj) * 68 + r] + bsm[24 + jj];
            float f  = fsig(gf);
            float ii = fsig(gi);
            float oo = fsig(go);
            float aa = ftanh(ga);
            float cn = f * csm[idx] + ii * aa;
            float hv = ftanh(cn) * oo;
            csm[idx] = cn;
            size_t ob = ((size_t)r * SS + s) * HH + j0 + jj;
            out[ob] = hv;                               // hs [B,S,H]
            out[(size_t)BB * SS * HH + ob] = cn;        // cs [B,S,H]
            hnxt[r * HH + j0 + jj] = wmma::__float_to_tf32(hv);
        }
        grid_sync(NB);
    }
}

// ---------------------------------------------------------------------------
extern "C" void kernel_launch(void* const* d_in, const int* in_sizes, int n_in,
                              void* d_out, int out_size)
{
    const float* x    = (const float*)d_in[0];
    const float* h0   = (const float*)d_in[1];
    const float* c0   = (const float*)d_in[2];
    const float* Win  = (const float*)d_in[3];
    const float* Whid = (const float*)d_in[4];
    const float* bias = (const float*)d_in[5];
    float* out = (float*)d_out;

    const int SMEM1 = (2 * 128 * 40 + 2 * 32 * 136) * 4;                  // 75776 B
    const int SMEM2 = (1024 * 36 + 4 * 64 * 36 + 2 * 64 * 36
                       + 32 * 68 + 512 + 32) * 4;                         // 213632 B

    cudaFuncSetAttribute(xw_gemm,  cudaFuncAttributeMaxDynamicSharedMemorySize, SMEM1);
    cudaFuncSetAttribute(lstm_rec, cudaFuncAttributeMaxDynamicSharedMemorySize, SMEM2);

    // Phase 1: xg = x @ W_in  -> [S][4][H][B]
    xw_gemm<<<dim3(32, 256), 256, SMEM1>>>(x, Win);

    // Phase 2: persistent recurrence, 128 blocks (1/SM, co-resident)
    lstm_rec<<<128, 256, SMEM2>>>(h0, c0, Whid, bias, out);
}